// round 11
// baseline (speedup 1.0000x reference)
#include <cuda_runtime.h>
#include <cuda_bf16.h>
#include <cstdint>
#include <mma.h>
using namespace nvcuda;

#define RCH 64
#define GCH 128
#define ACH 80
#define SCH 64
#define TT 8192
#define BB 8
#define NPOS (BB*TT)          // 65536
#define NLAYERS 30
#define NT 64                 // positions per block tile
#define NPAD 72               // padded position stride (elements)
#define THR 512
#define WPERL 43008           // 336*128 weights per layer

// smem regions (bytes):
//   OW (hi|lo 128x72 bf16):  [0, 36864)
//   W chunk (hi|lo):         [36864, 81920)   (fsm f32 overlays when W dead)
//   X/Z (hi|lo):             [81920, 104960)
#define SM_W 36864
#define SM_X 81920
#define SMEM_TOTAL 104960

__device__ float g_xa[BB*RCH*TT];
__device__ float g_xb[BB*RCH*TT];
__device__ float g_skip[BB*SCH*TT];
// bf16 hi/lo planes of x (ping-pong) and cond
__device__ __nv_bfloat16 g_xh0[BB*RCH*TT];
__device__ __nv_bfloat16 g_xl0[BB*RCH*TT];
__device__ __nv_bfloat16 g_xh1[BB*RCH*TT];
__device__ __nv_bfloat16 g_xl1[BB*RCH*TT];
__device__ __nv_bfloat16 g_ch[BB*ACH*TT];
__device__ __nv_bfloat16 g_cl[BB*ACH*TT];

// pre-split weights, chunk-contiguous per layer:
// tap0 [0,8192), tap1 [8192,16384), tap2 [16384,24576),
// aux [24576,34816) (m*80+kk), out [34816,43008) (m*64+kk)
__device__ __nv_bfloat16 g_wh[(size_t)NLAYERS * WPERL];
__device__ __nv_bfloat16 g_wl[(size_t)NLAYERS * WPERL];

static __device__ __forceinline__ float tanhapx(float x) {
    float r; asm("tanh.approx.f32 %0, %1;" : "=f"(r) : "f"(x)); return r;
}
static __device__ __forceinline__ float gatef(float a, float b) {
    return tanhapx(a) * (0.5f * tanhapx(0.5f * b) + 0.5f);
}

// ---------------------------------------------------------------------------
__global__ void k_prep(const float* __restrict__ cw, const float* __restrict__ aw,
                       const float* __restrict__ ow) {
    int idx = blockIdx.x * blockDim.x + threadIdx.x;
    if (idx >= NLAYERS * WPERL) return;
    int j = idx % WPERL;
    int l = idx / WPERL;
    float v;
    if (j < 24576) {
        int tap = j >> 13, jj = j & 8191;
        int m = jj >> 6, kk = jj & 63;
        v = cw[((size_t)(l * GCH + m) * RCH + kk) * 3 + tap];
    } else if (j < 34816) {
        int jj = j - 24576;
        int m = jj / 80, kk = jj - m * 80;
        v = aw[(size_t)(l * GCH + m) * ACH + kk];
    } else {
        int jj = j - 34816;
        int m = jj >> 6, kk = jj & 63;
        v = ow[(size_t)(l * GCH + m) * 64 + kk];
    }
    __nv_bfloat16 h = __float2bfloat16(v);
    g_wh[idx] = h;
    g_wl[idx] = __float2bfloat16(v - __bfloat162float(h));
}

// cond -> bf16 hi/lo planes (one-shot)
__global__ void k_prep_c(const float* __restrict__ cond) {
    int idx = blockIdx.x * blockDim.x + threadIdx.x;
    if (idx >= BB * ACH * TT) return;
    float v = cond[idx];
    __nv_bfloat16 h = __float2bfloat16(v);
    g_ch[idx] = h;
    g_cl[idx] = __float2bfloat16(v - __bfloat162float(h));
}

// ---------------------------------------------------------------------------
__global__ void k_first(const float* __restrict__ x,
                        const float* __restrict__ fw,
                        const float* __restrict__ fb) {
    int idx = blockIdx.x * blockDim.x + threadIdx.x;
    int r = idx >> 16;
    int p = idx & (NPOS - 1);
    int b = p >> 13;
    int t = p & (TT - 1);
    float v = fw[r] * x[p] + fb[r];
    size_t xi = (size_t)(b * RCH + r) * TT + t;
    g_xa[xi] = v;
    __nv_bfloat16 h = __float2bfloat16(v);
    g_xh0[xi] = h;
    g_xl0[xi] = __float2bfloat16(v - __bfloat162float(h));
    g_skip[(size_t)(b * SCH + r) * TT + t] = 0.f;
}

// ---------------------------------------------------------------------------
template<int S, int SPAD>
static __device__ __forceinline__ void stage_w(
        const __nv_bfloat16* __restrict__ gh,
        const __nv_bfloat16* __restrict__ gl,
        __nv_bfloat16* wa, int tid) {
    const unsigned int* sh = (const unsigned int*)gh;
    const unsigned int* sl = (const unsigned int*)gl;
    unsigned int* dh = (unsigned int*)wa;
    unsigned int* dl = dh + 128 * (SPAD / 2);
    constexpr int s2 = S / 2, sp2 = SPAD / 2;
#pragma unroll 1
    for (int idx = tid; idx < 128 * s2; idx += THR) {
        int m = idx / s2, kp = idx - m * s2;
        dh[m * sp2 + kp] = sh[idx];
        dl[m * sp2 + kp] = sl[idx];
    }
}

// ---------------------------------------------------------------------------
// bf16x3 mma over one staged chunk. acc[2] covers n0..n0+31.
// ---------------------------------------------------------------------------
template<int SPAD, int KS>
static __device__ __forceinline__ void mma_chunk(
        wmma::fragment<wmma::accumulator, 16, 16, 16, float> (&acc)[2],
        const __nv_bfloat16* __restrict__ wh, const __nv_bfloat16* __restrict__ wl,
        const __nv_bfloat16* __restrict__ xh, const __nv_bfloat16* __restrict__ xl,
        int m0, int n0) {
#pragma unroll 1
    for (int ks = 0; ks < KS; ks++) {
        wmma::fragment<wmma::matrix_a, 16, 16, 16, __nv_bfloat16, wmma::row_major> ah, al;
        wmma::load_matrix_sync(ah, wh + m0 * SPAD + 16 * ks, SPAD);
        wmma::load_matrix_sync(al, wl + m0 * SPAD + 16 * ks, SPAD);
#pragma unroll
        for (int nt = 0; nt < 2; nt++) {
            wmma::fragment<wmma::matrix_b, 16, 16, 16, __nv_bfloat16, wmma::row_major> bf;
            const int bo = 16 * ks * NPAD + n0 + 16 * nt;
            wmma::load_matrix_sync(bf, xh + bo, NPAD);
            wmma::mma_sync(acc[nt], ah, bf, acc[nt]);
            wmma::mma_sync(acc[nt], al, bf, acc[nt]);
            wmma::load_matrix_sync(bf, xl + bo, NPAD);
            wmma::mma_sync(acc[nt], ah, bf, acc[nt]);
        }
    }
}

// ---------------------------------------------------------------------------
// fused layer. warp: m0 = (w&7)*16, n0 = (w>>3)*32, acc[2].
// ---------------------------------------------------------------------------
__global__ void __launch_bounds__(THR, 2)
k_layer(int l, int d, int flip,
        const float* __restrict__ conv_b, const float* __restrict__ out_b,
        const float* __restrict__ mask) {
    extern __shared__ char smraw[];
    __nv_bfloat16* owp = (__nv_bfloat16*)smraw;                 // OW hi|lo
    __nv_bfloat16* wa  = (__nv_bfloat16*)(smraw + SM_W);        // W chunk
    __nv_bfloat16* xbh = (__nv_bfloat16*)(smraw + SM_X);        // X/Z hi|lo
    float* fsm = (float*)(smraw + SM_W);                        // overlays W

    const float* xin  = flip ? g_xb : g_xa;
    float*       xout = flip ? g_xa : g_xb;
    const __nv_bfloat16* iph = flip ? g_xh1 : g_xh0;
    const __nv_bfloat16* ipl = flip ? g_xl1 : g_xl0;
    __nv_bfloat16* oph = flip ? g_xh0 : g_xh1;
    __nv_bfloat16* opl = flip ? g_xl0 : g_xl1;

    const int tid  = threadIdx.x;
    const int wid  = tid >> 5;
    const int m0   = (wid & 7) * 16;
    const int n0   = (wid >> 3) * 32;
    const int p0   = blockIdx.x * NT;
    const int b    = p0 >> 13;
    const int tb   = p0 & (TT - 1);

    const __nv_bfloat16* gwh = g_wh + (size_t)l * WPERL;
    const __nv_bfloat16* gwl = g_wl + (size_t)l * WPERL;

    // OW staged once into its own region
    stage_w<64, 72>(gwh + 34816, gwl + 34816, owp, tid);

    wmma::fragment<wmma::accumulator, 16, 16, 16, float> acc[2];
    wmma::fill_fragment(acc[0], 0.f);
    wmma::fill_fragment(acc[1], 0.f);

    const __nv_bfloat16* xbase_h = iph + (size_t)b * RCH * TT;
    const __nv_bfloat16* xbase_l = ipl + (size_t)b * RCH * TT;
    __nv_bfloat16* xh = xbh;
    __nv_bfloat16* xl = xbh + 80 * NPAD;

    // ===== GEMM1 conv taps (S=64) ============================================
#pragma unroll 1
    for (int ch = 0; ch < 3; ch++) {
        __syncthreads();
        stage_w<64, 72>(gwh + ch * 8192, gwl + ch * 8192, wa, tid);
        const int off = (ch - 1) * d;
        if ((off & 1) == 0) {
            // aligned u32 path (2 positions per op; off even => never split)
#pragma unroll 1
            for (int idx = tid; idx < 64 * 32; idx += THR) {
                int kk = idx >> 5, q = idx & 31;
                int t0 = tb + 2 * q + off;
                unsigned int vh = 0, vl = 0;
                if ((unsigned)t0 < TT) {
                    vh = *(const unsigned int*)(xbase_h + (size_t)kk * TT + t0);
                    vl = *(const unsigned int*)(xbase_l + (size_t)kk * TT + t0);
                }
                *(unsigned int*)(xh + kk * NPAD + 2 * q) = vh;
                *(unsigned int*)(xl + kk * NPAD + 2 * q) = vl;
            }
        } else {
            // scalar path for odd offsets (d = 1)
            const __nv_bfloat16 z0 = __float2bfloat16(0.f);
#pragma unroll 1
            for (int idx = tid; idx < 64 * NT; idx += THR) {
                int kk = idx >> 6, pp = idx & 63;
                int t0 = tb + pp + off;
                bool ok = (unsigned)t0 < TT;
                xh[kk * NPAD + pp] = ok ? xbase_h[(size_t)kk * TT + t0] : z0;
                xl[kk * NPAD + pp] = ok ? xbase_l[(size_t)kk * TT + t0] : z0;
            }
        }
        __syncthreads();
        mma_chunk<72, 4>(acc, wa, wa + 128 * 72, xh, xl, m0, n0);
    }

    // ===== GEMM1 aux (S=80), 16B copies ======================================
    __syncthreads();
    stage_w<80, 88>(gwh + 24576, gwl + 24576, wa, tid);
    {
        const __nv_bfloat16* cbh = g_ch + (size_t)b * ACH * TT + tb;
        const __nv_bfloat16* cbl = g_cl + (size_t)b * ACH * TT + tb;
#pragma unroll 1
        for (int idx = tid; idx < 80 * 8; idx += THR) {
            int kk = idx >> 3, j = idx & 7;
            *(ulonglong2*)(xh + kk * NPAD + 8 * j) =
                *(const ulonglong2*)(cbh + (size_t)kk * TT + 8 * j);
            *(ulonglong2*)(xl + kk * NPAD + 8 * j) =
                *(const ulonglong2*)(cbl + (size_t)kk * TT + 8 * j);
        }
    }
    __syncthreads();
    mma_chunk<88, 5>(acc, wa, wa + 128 * 88, xh, xl, m0, n0);
    __syncthreads();   // W region dead; becomes fsm

    // ===== H -> fsm ==========================================================
    wmma::store_matrix_sync(fsm + m0 * NPAD + n0,      acc[0], NPAD, wmma::mem_row_major);
    wmma::store_matrix_sync(fsm + m0 * NPAD + n0 + 16, acc[1], NPAD, wmma::mem_row_major);
    __syncthreads();

    // ===== gate -> Z =========================================================
    {
        const float* cbp = conv_b + l * GCH;
#pragma unroll 1
        for (int idx = tid; idx < 64 * NT; idx += THR) {
            int c = idx >> 6, pp = idx & 63;
            float a = fsm[c * NPAD + pp] + cbp[c];
            float g = fsm[(c + 64) * NPAD + pp] + cbp[c + 64];
            float z = gatef(a, g);
            __nv_bfloat16 h = __float2bfloat16(z);
            xh[c * NPAD + pp] = h;
            xl[c * NPAD + pp] = __float2bfloat16(z - __bfloat162float(h));
        }
    }
    wmma::fill_fragment(acc[0], 0.f);
    wmma::fill_fragment(acc[1], 0.f);
    __syncthreads();

    // ===== GEMM2: out projection (K=64), OW pre-staged =======================
    mma_chunk<72, 4>(acc, owp, owp + 128 * 72, xh, xl, m0, n0);
    wmma::store_matrix_sync(fsm + m0 * NPAD + n0,      acc[0], NPAD, wmma::mem_row_major);
    wmma::store_matrix_sync(fsm + m0 * NPAD + n0 + 16, acc[1], NPAD, wmma::mem_row_major);
    __syncthreads();

    // ===== epilogue: bias, mask, residual(+planes), skip =====================
    {
        const float* obp = out_b + l * (RCH + SCH);
#pragma unroll 1
        for (int idx = tid; idx < 128 * NT; idx += THR) {
            int r = idx >> 6, pp = idx & 63;
            float o = fsm[r * NPAD + pp] + obp[r];
            float m = mask[p0 + pp];
            if (r < RCH) {
                size_t xi = ((size_t)(b * RCH + r) << 13) + tb + pp;
                float val = fmaf(o, m, xin[xi]);
                xout[xi] = val;
                __nv_bfloat16 h = __float2bfloat16(val);
                oph[xi] = h;
                opl[xi] = __float2bfloat16(val - __bfloat162float(h));
            } else {
                size_t si = ((size_t)(b * SCH + r - RCH) << 13) + tb + pp;
                g_skip[si] += o * m;
            }
        }
    }
}

// ---------------------------------------------------------------------------
__global__ void k_last(const float* __restrict__ w1, const float* __restrict__ b1,
                       const float* __restrict__ w2, const float* __restrict__ b2,
                       float* __restrict__ out) {
    __shared__ float w1t[64 * 64];
    __shared__ float w2s[64];
    __shared__ float b1s[64];
    const int tid = threadIdx.x;
    for (int idx = tid; idx < 64 * 64; idx += 256) {
        int i = idx >> 6, j = idx & 63;
        w1t[i * 64 + j] = w1[j * 64 + i];
    }
    if (tid < 64) { w2s[tid] = w2[tid]; b1s[tid] = b1[tid]; }
    __syncthreads();

    const int p = blockIdx.x * 256 + tid;
    const int b = p >> 13;
    const int t = p & (TT - 1);

    float acc[64];
#pragma unroll
    for (int j = 0; j < 64; j++) acc[j] = b1s[j];

    const float* sp = g_skip + (size_t)b * SCH * TT + t;
    for (int i = 0; i < 64; i++) {
        float sv = fmaxf(sp[i * TT], 0.f);
#pragma unroll
        for (int j = 0; j < 64; j += 4) {
            float4 w = *(const float4*)(w1t + i * 64 + j);
            acc[j]     = fmaf(w.x, sv, acc[j]);
            acc[j + 1] = fmaf(w.y, sv, acc[j + 1]);
            acc[j + 2] = fmaf(w.z, sv, acc[j + 2]);
            acc[j + 3] = fmaf(w.w, sv, acc[j + 3]);
        }
    }
    float y = b2[0];
#pragma unroll
    for (int j = 0; j < 64; j++) y = fmaf(w2s[j], fmaxf(acc[j], 0.f), y);
    out[p] = y;
}

// ---------------------------------------------------------------------------
extern "C" void kernel_launch(void* const* d_in, const int* in_sizes, int n_in,
                              void* d_out, int out_size) {
    const float* x      = (const float*)d_in[0];
    const float* x_mask = (const float*)d_in[1];
    const float* c      = (const float*)d_in[2];
    const float* fw     = (const float*)d_in[3];
    const float* fb     = (const float*)d_in[4];
    const float* conv_w = (const float*)d_in[5];
    const float* conv_b = (const float*)d_in[6];
    const float* aux_w  = (const float*)d_in[7];
    const float* out_w  = (const float*)d_in[8];
    const float* out_b  = (const float*)d_in[9];
    const float* w1     = (const float*)d_in[10];
    const float* b1     = (const float*)d_in[11];
    const float* w2     = (const float*)d_in[12];
    const float* b2     = (const float*)d_in[13];

    cudaFuncSetAttribute(k_layer, cudaFuncAttributeMaxDynamicSharedMemorySize,
                         SMEM_TOTAL);

    int nprep = NLAYERS * WPERL;
    k_prep<<<(nprep + 511) / 512, 512>>>(conv_w, aux_w, out_w);
    k_prep_c<<<(BB * ACH * TT + 511) / 512, 512>>>(c);
    k_first<<<(RCH * NPOS) / 512, 512>>>(x, fw, fb);

    for (int l = 0; l < NLAYERS; l++) {
        int d = 1 << (l % 10);
        k_layer<<<NPOS / NT, THR, SMEM_TOTAL>>>(
            l, d, l & 1, conv_b, out_b, x_mask);
    }

    k_last<<<NPOS / 256, 256>>>(w1, b1, w2, b2, (float*)d_out);
}

// round 12
// speedup vs baseline: 1.3133x; 1.3133x over previous
#include <cuda_runtime.h>
#include <cuda_bf16.h>
#include <cstdint>
#include <mma.h>
using namespace nvcuda;

#define RCH 64
#define GCH 128
#define ACH 80
#define SCH 64
#define TT 8192
#define BB 8
#define NPOS (BB*TT)          // 65536
#define NLAYERS 30
#define NT 64                 // positions per block tile
#define NPAD 72
#define THR 512
#define WPERL 43008

// double buffers: each = W(128x72 hi|lo bf16 = 36864 B) + X(64x72 hi|lo = 18432 B)
#define BUF_BYTES 55296
#define BW_LO (128*72)        // elements: lo-plane offset inside W region
#define BX_OFF 36864          // bytes: X region offset inside a buffer
#define BX_LO (64*72)         // elements: lo-plane offset inside X region
#define SMEM_TOTAL (2*BUF_BYTES)   // 110592

__device__ float g_xa[BB*RCH*TT];
__device__ float g_xb[BB*RCH*TT];
__device__ float g_skip[BB*SCH*TT];
__device__ __nv_bfloat16 g_xh0[BB*RCH*TT];
__device__ __nv_bfloat16 g_xl0[BB*RCH*TT];
__device__ __nv_bfloat16 g_xh1[BB*RCH*TT];
__device__ __nv_bfloat16 g_xl1[BB*RCH*TT];
__device__ __nv_bfloat16 g_ch[BB*ACH*TT];
__device__ __nv_bfloat16 g_cl[BB*ACH*TT];

// pre-split weights, chunk-contiguous per layer:
// tap0 [0,8192) tap1 [8192,16384) tap2 [16384,24576)
// auxA [24576,30720) 128x48   auxB [30720,34816) 128x32   out [34816,43008) 128x64
__device__ __nv_bfloat16 g_wh[(size_t)NLAYERS * WPERL];
__device__ __nv_bfloat16 g_wl[(size_t)NLAYERS * WPERL];

static __device__ __forceinline__ float tanhapx(float x) {
    float r; asm("tanh.approx.f32 %0, %1;" : "=f"(r) : "f"(x)); return r;
}
static __device__ __forceinline__ float gatef(float a, float b) {
    return tanhapx(a) * (0.5f * tanhapx(0.5f * b) + 0.5f);
}

// ---- cp.async helpers -------------------------------------------------------
static __device__ __forceinline__ void cpa16(unsigned int d, const void* s, bool p) {
    asm volatile("cp.async.cg.shared.global [%0], [%1], 16, %2;"
                 :: "r"(d), "l"(s), "r"(p ? 16 : 0));
}
static __device__ __forceinline__ void cpa4(unsigned int d, const void* s, bool p) {
    asm volatile("cp.async.ca.shared.global [%0], [%1], 4, %2;"
                 :: "r"(d), "l"(s), "r"(p ? 4 : 0));
}
static __device__ __forceinline__ void cp_commit() {
    asm volatile("cp.async.commit_group;");
}
template<int N>
static __device__ __forceinline__ void cp_wait() {
    asm volatile("cp.async.wait_group %0;" :: "n"(N));
}

// ---------------------------------------------------------------------------
__global__ void k_prep(const float* __restrict__ cw, const float* __restrict__ aw,
                       const float* __restrict__ ow) {
    int idx = blockIdx.x * blockDim.x + threadIdx.x;
    if (idx >= NLAYERS * WPERL) return;
    int j = idx % WPERL;
    int l = idx / WPERL;
    float v;
    if (j < 24576) {
        int tap = j >> 13, jj = j & 8191;
        int m = jj >> 6, kk = jj & 63;
        v = cw[((size_t)(l * GCH + m) * RCH + kk) * 3 + tap];
    } else if (j < 30720) {
        int jj = j - 24576;
        int m = jj / 48, kk = jj - m * 48;
        v = aw[(size_t)(l * GCH + m) * ACH + kk];
    } else if (j < 34816) {
        int jj = j - 30720;
        int m = jj >> 5, kk = jj & 31;
        v = aw[(size_t)(l * GCH + m) * ACH + 48 + kk];
    } else {
        int jj = j - 34816;
        int m = jj >> 6, kk = jj & 63;
        v = ow[(size_t)(l * GCH + m) * 64 + kk];
    }
    __nv_bfloat16 h = __float2bfloat16(v);
    g_wh[idx] = h;
    g_wl[idx] = __float2bfloat16(v - __bfloat162float(h));
}

__global__ void k_prep_c(const float* __restrict__ cond) {
    int idx = blockIdx.x * blockDim.x + threadIdx.x;
    if (idx >= BB * ACH * TT) return;
    float v = cond[idx];
    __nv_bfloat16 h = __float2bfloat16(v);
    g_ch[idx] = h;
    g_cl[idx] = __float2bfloat16(v - __bfloat162float(h));
}

__global__ void k_first(const float* __restrict__ x,
                        const float* __restrict__ fw,
                        const float* __restrict__ fb) {
    int idx = blockIdx.x * blockDim.x + threadIdx.x;
    int r = idx >> 16;
    int p = idx & (NPOS - 1);
    int b = p >> 13;
    int t = p & (TT - 1);
    float v = fw[r] * x[p] + fb[r];
    size_t xi = (size_t)(b * RCH + r) * TT + t;
    g_xa[xi] = v;
    __nv_bfloat16 h = __float2bfloat16(v);
    g_xh0[xi] = h;
    g_xl0[xi] = __float2bfloat16(v - __bfloat162float(h));
    g_skip[(size_t)(b * SCH + r) * TT + t] = 0.f;
}

// ---- async W staging: 128 x S (hi & lo) -> SPAD-strided smem -----------------
template<int S>
static __device__ __forceinline__ void stage_w_async(
        const __nv_bfloat16* __restrict__ gh,
        const __nv_bfloat16* __restrict__ gl,
        unsigned int wsm, int tid) {
    constexpr int SPAD = S + 8;
    constexpr int CHK = S / 8;        // 16B chunks per row
    constexpr int TOT = 128 * CHK;
    unsigned int dlo = wsm + BW_LO * 2;
    for (int i = tid; i < TOT; i += THR) {
        int m = i / CHK, j = i - m * CHK;
        unsigned int doff = m * (SPAD * 2) + j * 16;
        size_t soff = (size_t)m * S + j * 8;
        cpa16(wsm + doff, gh + soff, true);
        cpa16(dlo + doff, gl + soff, true);
    }
}

// ---- X staging for conv taps (64 rows) ---------------------------------------
static __device__ __forceinline__ void stage_x_conv(
        const __nv_bfloat16* __restrict__ ph, const __nv_bfloat16* __restrict__ pl,
        __nv_bfloat16* xbuf, int tb, int off, int tid) {
    unsigned int xsm = (unsigned int)__cvta_generic_to_shared(xbuf);
    unsigned int dlo = xsm + BX_LO * 2;
    if ((off & 7) == 0) {
        int kk = tid >> 3, j = tid & 7;                 // 512 = 64*8
        int t0 = tb + j * 8 + off;
        bool ok = (unsigned)t0 <= (unsigned)(TT - 8);
        size_t so = (size_t)kk * TT + (ok ? t0 : 0);
        unsigned int doff = (unsigned int)(kk * NPAD + j * 8) * 2;
        cpa16(xsm + doff, ph + so, ok);
        cpa16(dlo + doff, pl + so, ok);
    } else if ((off & 1) == 0) {
        for (int i = tid; i < 2048; i += THR) {
            int kk = i >> 5, q = i & 31;
            int t0 = tb + 2 * q + off;
            bool ok = (unsigned)t0 <= (unsigned)(TT - 2);
            size_t so = (size_t)kk * TT + (ok ? t0 : 0);
            unsigned int doff = (unsigned int)(kk * NPAD + 2 * q) * 2;
            cpa4(xsm + doff, ph + so, ok);
            cpa4(dlo + doff, pl + so, ok);
        }
    } else {
        // d == 1: synchronous scalar fallback
        const __nv_bfloat16 z0 = __float2bfloat16(0.f);
        __nv_bfloat16* xl = xbuf + BX_LO;
        for (int i = tid; i < 4096; i += THR) {
            int kk = i >> 6, pp = i & 63;
            int t0 = tb + pp + off;
            bool ok = (unsigned)t0 < TT;
            size_t so = (size_t)kk * TT + (ok ? t0 : 0);
            xbuf[kk * NPAD + pp] = ok ? ph[so] : z0;
            xl[kk * NPAD + pp]   = ok ? pl[so] : z0;
        }
    }
}

// ---- X staging for aux rows (nrows x 8 chunks, always aligned) ---------------
static __device__ __forceinline__ void stage_x_aux(
        const __nv_bfloat16* __restrict__ ph, const __nv_bfloat16* __restrict__ pl,
        __nv_bfloat16* xbuf, int nrows, int tid) {
    unsigned int xsm = (unsigned int)__cvta_generic_to_shared(xbuf);
    unsigned int dlo = xsm + BX_LO * 2;
    int tot = nrows * 8;
    for (int i = tid; i < tot; i += THR) {
        int kk = i >> 3, j = i & 7;
        size_t so = (size_t)kk * TT + j * 8;
        unsigned int doff = (unsigned int)(kk * NPAD + j * 8) * 2;
        cpa16(xsm + doff, ph + so, true);
        cpa16(dlo + doff, pl + so, true);
    }
}

// ---- bf16x3 mma over one staged chunk ----------------------------------------
template<int SPAD, int KS>
static __device__ __forceinline__ void mma_chunk(
        wmma::fragment<wmma::accumulator, 16, 16, 16, float> (&acc)[2],
        const __nv_bfloat16* __restrict__ wh, const __nv_bfloat16* __restrict__ wl,
        const __nv_bfloat16* __restrict__ xh, const __nv_bfloat16* __restrict__ xl,
        int m0, int n0) {
#pragma unroll 1
    for (int ks = 0; ks < KS; ks++) {
        wmma::fragment<wmma::matrix_a, 16, 16, 16, __nv_bfloat16, wmma::row_major> ah, al;
        wmma::load_matrix_sync(ah, wh + m0 * SPAD + 16 * ks, SPAD);
        wmma::load_matrix_sync(al, wl + m0 * SPAD + 16 * ks, SPAD);
#pragma unroll
        for (int nt = 0; nt < 2; nt++) {
            wmma::fragment<wmma::matrix_b, 16, 16, 16, __nv_bfloat16, wmma::row_major> bf;
            const int bo = 16 * ks * NPAD + n0 + 16 * nt;
            wmma::load_matrix_sync(bf, xh + bo, NPAD);
            wmma::mma_sync(acc[nt], ah, bf, acc[nt]);
            wmma::mma_sync(acc[nt], al, bf, acc[nt]);
            wmma::load_matrix_sync(bf, xl + bo, NPAD);
            wmma::mma_sync(acc[nt], ah, bf, acc[nt]);
        }
    }
}

// ---------------------------------------------------------------------------
__global__ void __launch_bounds__(THR, 2)
k_layer(int l, int d, int flip,
        const float* __restrict__ conv_b, const float* __restrict__ out_b,
        const float* __restrict__ mask) {
    extern __shared__ char smraw[];

    const float* xin  = flip ? g_xb : g_xa;
    float*       xout = flip ? g_xa : g_xb;
    const __nv_bfloat16* iph = flip ? g_xh1 : g_xh0;
    const __nv_bfloat16* ipl = flip ? g_xl1 : g_xl0;
    __nv_bfloat16* oph = flip ? g_xh0 : g_xh1;
    __nv_bfloat16* opl = flip ? g_xl0 : g_xl1;

    const int tid  = threadIdx.x;
    const int wid  = tid >> 5;
    const int m0   = (wid & 7) * 16;
    const int n0   = (wid >> 3) * 32;
    const int p0   = blockIdx.x * NT;
    const int b    = p0 >> 13;
    const int tb   = p0 & (TT - 1);

    const __nv_bfloat16* gwh = g_wh + (size_t)l * WPERL;
    const __nv_bfloat16* gwl = g_wl + (size_t)l * WPERL;
    const __nv_bfloat16* xbase_h = iph + (size_t)b * RCH * TT;
    const __nv_bfloat16* xbase_l = ipl + (size_t)b * RCH * TT;
    const __nv_bfloat16* cbh = g_ch + (size_t)b * ACH * TT + tb;
    const __nv_bfloat16* cbl = g_cl + (size_t)b * ACH * TT + tb;

    __nv_bfloat16* bufW[2] = { (__nv_bfloat16*)smraw,
                               (__nv_bfloat16*)(smraw + BUF_BYTES) };
    __nv_bfloat16* bufX[2] = { (__nv_bfloat16*)(smraw + BX_OFF),
                               (__nv_bfloat16*)(smraw + BUF_BYTES + BX_OFF) };
    float* fsm = (float*)smraw;   // overlays buf0 after its last read

    auto issue = [&](int ch) {
        unsigned int wsm = (unsigned int)__cvta_generic_to_shared(bufW[ch & 1]);
        switch (ch) {
        case 0: case 1: case 2:
            stage_w_async<64>(gwh + ch * 8192, gwl + ch * 8192, wsm, tid);
            stage_x_conv(xbase_h, xbase_l, bufX[ch & 1], tb, (ch - 1) * d, tid);
            break;
        case 3:
            stage_w_async<48>(gwh + 24576, gwl + 24576, wsm, tid);
            stage_x_aux(cbh, cbl, bufX[1], 48, tid);
            break;
        case 4:
            stage_w_async<32>(gwh + 30720, gwl + 30720, wsm, tid);
            stage_x_aux(cbh + (size_t)48 * TT, cbl + (size_t)48 * TT,
                        bufX[0], 32, tid);
            break;
        case 5:
            stage_w_async<64>(gwh + 34816, gwl + 34816, wsm, tid);
            break;
        }
        cp_commit();
    };

    wmma::fragment<wmma::accumulator, 16, 16, 16, float> acc[2];
    wmma::fill_fragment(acc[0], 0.f);
    wmma::fill_fragment(acc[1], 0.f);

    issue(0);
    issue(1);
#pragma unroll 1
    for (int ch = 0; ch < 5; ch++) {
        cp_wait<1>();
        __syncthreads();
        __nv_bfloat16* W = bufW[ch & 1];
        __nv_bfloat16* X = bufX[ch & 1];
        if (ch < 3)       mma_chunk<72, 4>(acc, W, W + BW_LO, X, X + BX_LO, m0, n0);
        else if (ch == 3) mma_chunk<56, 3>(acc, W, W + BW_LO, X, X + BX_LO, m0, n0);
        else              mma_chunk<40, 2>(acc, W, W + BW_LO, X, X + BX_LO, m0, n0);
        __syncthreads();
        if (ch <= 3) issue(ch + 2);
    }
    cp_wait<0>();   // OW (group 5) complete

    // ===== H -> fsm (buf0 dead) =============================================
    wmma::store_matrix_sync(fsm + m0 * NPAD + n0,      acc[0], NPAD, wmma::mem_row_major);
    wmma::store_matrix_sync(fsm + m0 * NPAD + n0 + 16, acc[1], NPAD, wmma::mem_row_major);
    __syncthreads();

    // ===== gate -> Z (into buf1.X) ==========================================
    {
        __nv_bfloat16* zh = bufX[1];
        __nv_bfloat16* zl = bufX[1] + BX_LO;
        const float* cbp = conv_b + l * GCH;
#pragma unroll 1
        for (int idx = tid; idx < 64 * NT; idx += THR) {
            int c = idx >> 6, pp = idx & 63;
            float a = fsm[c * NPAD + pp] + cbp[c];
            float g = fsm[(c + 64) * NPAD + pp] + cbp[c + 64];
            float z = gatef(a, g);
            __nv_bfloat16 h = __float2bfloat16(z);
            zh[c * NPAD + pp] = h;
            zl[c * NPAD + pp] = __float2bfloat16(z - __bfloat162float(h));
        }
    }
    wmma::fill_fragment(acc[0], 0.f);
    wmma::fill_fragment(acc[1], 0.f);
    __syncthreads();

    // ===== GEMM2: OW (buf1.W) x Z (buf1.X) ==================================
    mma_chunk<72, 4>(acc, bufW[1], bufW[1] + BW_LO, bufX[1], bufX[1] + BX_LO, m0, n0);
    wmma::store_matrix_sync(fsm + m0 * NPAD + n0,      acc[0], NPAD, wmma::mem_row_major);
    wmma::store_matrix_sync(fsm + m0 * NPAD + n0 + 16, acc[1], NPAD, wmma::mem_row_major);
    __syncthreads();

    // ===== epilogue ==========================================================
    {
        const float* obp = out_b + l * (RCH + SCH);
#pragma unroll 1
        for (int idx = tid; idx < 128 * NT; idx += THR) {
            int r = idx >> 6, pp = idx & 63;
            float o = fsm[r * NPAD + pp] + obp[r];
            float m = mask[p0 + pp];
            if (r < RCH) {
                size_t xi = ((size_t)(b * RCH + r) << 13) + tb + pp;
                float val = fmaf(o, m, xin[xi]);
                xout[xi] = val;
                __nv_bfloat16 h = __float2bfloat16(val);
                oph[xi] = h;
                opl[xi] = __float2bfloat16(val - __bfloat162float(h));
            } else {
                size_t si = ((size_t)(b * SCH + r - RCH) << 13) + tb + pp;
                g_skip[si] += o * m;
            }
        }
    }
}

// ---------------------------------------------------------------------------
__global__ void k_last(const float* __restrict__ w1, const float* __restrict__ b1,
                       const float* __restrict__ w2, const float* __restrict__ b2,
                       float* __restrict__ out) {
    __shared__ float w1t[64 * 64];
    __shared__ float w2s[64];
    __shared__ float b1s[64];
    const int tid = threadIdx.x;
    for (int idx = tid; idx < 64 * 64; idx += 256) {
        int i = idx >> 6, j = idx & 63;
        w1t[i * 64 + j] = w1[j * 64 + i];
    }
    if (tid < 64) { w2s[tid] = w2[tid]; b1s[tid] = b1[tid]; }
    __syncthreads();

    const int p = blockIdx.x * 256 + tid;
    const int b = p >> 13;
    const int t = p & (TT - 1);

    float acc[64];
#pragma unroll
    for (int j = 0; j < 64; j++) acc[j] = b1s[j];

    const float* sp = g_skip + (size_t)b * SCH * TT + t;
    for (int i = 0; i < 64; i++) {
        float sv = fmaxf(sp[i * TT], 0.f);
#pragma unroll
        for (int j = 0; j < 64; j += 4) {
            float4 w = *(const float4*)(w1t + i * 64 + j);
            acc[j]     = fmaf(w.x, sv, acc[j]);
            acc[j + 1] = fmaf(w.y, sv, acc[j + 1]);
            acc[j + 2] = fmaf(w.z, sv, acc[j + 2]);
            acc[j + 3] = fmaf(w.w, sv, acc[j + 3]);
        }
    }
    float y = b2[0];
#pragma unroll
    for (int j = 0; j < 64; j++) y = fmaf(w2s[j], fmaxf(acc[j], 0.f), y);
    out[p] = y;
}

// ---------------------------------------------------------------------------
extern "C" void kernel_launch(void* const* d_in, const int* in_sizes, int n_in,
                              void* d_out, int out_size) {
    const float* x      = (const float*)d_in[0];
    const float* x_mask = (const float*)d_in[1];
    const float* c      = (const float*)d_in[2];
    const float* fw     = (const float*)d_in[3];
    const float* fb     = (const float*)d_in[4];
    const float* conv_w = (const float*)d_in[5];
    const float* conv_b = (const float*)d_in[6];
    const float* aux_w  = (const float*)d_in[7];
    const float* out_w  = (const float*)d_in[8];
    const float* out_b  = (const float*)d_in[9];
    const float* w1     = (const float*)d_in[10];
    const float* b1     = (const float*)d_in[11];
    const float* w2     = (const float*)d_in[12];
    const float* b2     = (const float*)d_in[13];

    cudaFuncSetAttribute(k_layer, cudaFuncAttributeMaxDynamicSharedMemorySize,
                         SMEM_TOTAL);

    int nprep = NLAYERS * WPERL;
    k_prep<<<(nprep + 511) / 512, 512>>>(conv_w, aux_w, out_w);
    k_prep_c<<<(BB * ACH * TT + 511) / 512, 512>>>(c);
    k_first<<<(RCH * NPOS) / 512, 512>>>(x, fw, fb);

    for (int l = 0; l < NLAYERS; l++) {
        int d = 1 << (l % 10);
        k_layer<<<NPOS / NT, THR, SMEM_TOTAL>>>(
            l, d, l & 1, conv_b, out_b, x_mask);
    }

    k_last<<<NPOS / 256, 256>>>(w1, b1, w2, b2, (float*)d_out);
}